// round 14
// baseline (speedup 1.0000x reference)
#include <cuda_runtime.h>
#include <math.h>
#include <stdint.h>

// ============================================================================
// AttnBlock: SE(3)-attention edge softmax, D=2, C=2.
//  - radial MLP -> 2048-pt LUT (BN stats exact via moment histogram).
//  - fused aux chain; k_main = launch index 3 (ncu-profiled).
//  - k_main: warp per 2 edges, lean-L1 body (vector node/LUT, vector dst/dist)
//    + register diet (packed lane tables, short vec live ranges) to reach
//    3 CTAs/SM (24 warps/SM) for latency cover.
// ============================================================================

#define NB     2048
#define NLUT   2048
#define NMAX   50048
#define EPSV   1e-5f

__device__ float  g_hist[3 * NB];
__device__ float  g_AB[180];
__device__ double g_stats[540];
__device__ float  g_lut2[(size_t)(NLUT + 1) * 160];  // [i0][entry<80][{r_i0, r_i0+1}]
__device__ float  g_node[(size_t)NMAX * 40];         // qi[18] | fi[18] | pad4
__device__ float  g_s[NMAX];
__device__ uchar4 g_ct[288];   // contraction slot -> (arr, off, b2pair, qpair)
__device__ uchar4 g_bt[96];    // build slot -> (quad, fpos, pair, 0)

__constant__ int c_Roff4[9] = {0, 4, 8, 12, 16, 28, 40, 44, 56}; // p = l*3+k
__constant__ int c_SZ[9]    = {1, 3, 5, 3, 27, 45, 5, 45, 125};  // a = k*3+l

// ---- launch 0: tables + node transform + histogram -------------------------
__global__ void k_fused0(const float* __restrict__ f0, const float* __restrict__ f1,
                         const float* __restrict__ f2, const float* __restrict__ wq,
                         const float* __restrict__ dist, int N, int E) {
    if (blockIdx.x == 0 && threadIdx.x == 0) {
        const int LOFF2[3] = {0, 1, 4};
        const int FOFF2[3] = {0, 1, 4};
        int PB[9]; int pb = 0;
        for (int a = 0; a < 9; a++) {
            int k = a / 3, l = a % 3;
            int J = 2 * min(k, l) + 1, K2 = 2 * k + 1;
            PB[a] = pb; pb += J * K2;
        }
        // contraction table: 259 entries canonical order + zero padding
        int flat = 0;
        for (int a = 0; a < 9; a++) {
            int k = a / 3, l = a % 3;
            int J = 2 * min(k, l) + 1, K2 = 2 * k + 1, L2 = 2 * l + 1;
            int SZ = J * L2 * K2;
            for (int t = 0; t < SZ; t++) {
                int mk = t % K2, r = t / K2, ml = r % L2, j = r / L2;
                uchar4 c;
                c.x = (unsigned char)a;
                c.y = (unsigned char)t;
                c.z = (unsigned char)(PB[a] + j * K2 + mk);
                c.w = (unsigned char)(LOFF2[l] + ml);
                g_ct[flat++] = c;
            }
        }
        for (; flat < 288; flat++) g_ct[flat] = make_uchar4(0, 0, 0, 0);
        // build table: 69 entries + zero padding
        int s = 0;
        for (int a = 0; a < 9; a++) {
            int k = a / 3, l = a % 3;
            int J = 2 * min(k, l) + 1, K2 = 2 * k + 1;
            int p_lk = l * 3 + k;
            int quadbase = c_Roff4[p_lk] / 4;
            for (int j = 0; j < J; j++)
                for (int mk = 0; mk < K2; mk++) {
                    uchar4 c;
                    c.x = (unsigned char)(quadbase + j);
                    c.y = (unsigned char)(FOFF2[k] + mk);
                    c.z = (unsigned char)(PB[a] + j * K2 + mk);
                    c.w = 0;
                    g_bt[s++] = c;
                }
        }
        for (; s < 96; s++) g_bt[s] = make_uchar4(0, 0, 0, 0);
    }

    // node transform (stride 40, pad zeroed)
    int n = blockIdx.x * blockDim.x + threadIdx.x;
    if (n < N) {
        const float* F0 = f0 + (size_t)n * 2;
        const float* F1 = f1 + (size_t)n * 6;
        const float* F2 = f2 + (size_t)n * 10;
        float* o_ = g_node + (size_t)n * 40;
#pragma unroll
        for (int o = 0; o < 2; o++) {
            o_[2 * 0 + o] = wq[0 + o * 2 + 0] * F0[0] + wq[0 + o * 2 + 1] * F0[1];
#pragma unroll
            for (int m = 0; m < 3; m++)
                o_[2 * (1 + m) + o] = wq[4 + o * 2 + 0] * F1[m] + wq[4 + o * 2 + 1] * F1[3 + m];
#pragma unroll
            for (int m = 0; m < 5; m++)
                o_[2 * (4 + m) + o] = wq[8 + o * 2 + 0] * F2[m] + wq[8 + o * 2 + 1] * F2[5 + m];
        }
        float* fo = o_ + 18;
#pragma unroll
        for (int i = 0; i < 2; i++) fo[2 * 0 + i] = F0[i];
#pragma unroll
        for (int m = 0; m < 3; m++)
#pragma unroll
            for (int i = 0; i < 2; i++) fo[2 * (1 + m) + i] = F1[i * 3 + m];
#pragma unroll
        for (int m = 0; m < 5; m++)
#pragma unroll
            for (int i = 0; i < 2; i++) fo[2 * (4 + m) + i] = F2[i * 5 + m];
        o_[36] = 0.f; o_[37] = 0.f; o_[38] = 0.f; o_[39] = 0.f;
    }

    // histogram
    __shared__ float h[3 * NB];
    for (int i = threadIdx.x; i < 3 * NB; i += blockDim.x) h[i] = 0.f;
    __syncthreads();
    int i0 = blockIdx.x * blockDim.x + threadIdx.x, st = gridDim.x * blockDim.x;
    for (int e = i0; e < E; e += st) {
        float d = dist[e];
        int b = (int)(d * (float)NB);
        b = max(0, min(NB - 1, b));
        atomicAdd(&h[b], 1.f);
        atomicAdd(&h[NB + b], d);
        atomicAdd(&h[2 * NB + b], d * d);
    }
    __syncthreads();
    for (int j = threadIdx.x; j < 3 * NB; j += blockDim.x)
        if (h[j] != 0.f) atomicAdd(&g_hist[j], h[j]);
}

// ---- launch 1: dist mean/var + L1 affines + L2 stats slice -----------------
__global__ void k_statsAB(const float* __restrict__ rW1, const float* __restrict__ rg1,
                          const float* __restrict__ rbb1, const float* __restrict__ rW2,
                          const float* __restrict__ rb2, int E) {
    __shared__ double rs[3 * 288];
    __shared__ float sA[90], sB[90];
    __shared__ float smu, svar;
    int t = threadIdx.x;
    double c = 0, s1 = 0, s2 = 0;
    for (int b = t; b < NB; b += 288) {
        c  += (double)g_hist[b];
        s1 += (double)g_hist[NB + b];
        s2 += (double)g_hist[2 * NB + b];
    }
    rs[t] = c; rs[288 + t] = s1; rs[576 + t] = s2;
    __syncthreads();
    if (t == 0) {
        double t1 = 0, t2 = 0;
        for (int i = 0; i < 288; i++) { t1 += rs[288 + i]; t2 += rs[576 + i]; }
        double mu  = t1 / (double)E;
        double var = t2 / (double)E - mu * mu;
        if (var < 0) var = 0;
        smu = (float)mu; svar = (float)var;
    }
    __syncthreads();
    if (t < 90) {
        float w = rW1[t], gi = rg1[t];
        float inv = rsqrtf(svar * w * w + EPSV);
        sA[t] = w * gi * inv;
        sB[t] = rbb1[t] - w * smu * gi * inv;
        if (blockIdx.x == 0) { g_AB[t] = sA[t]; g_AB[90 + t] = sB[t]; }
    }
    __syncthreads();
    if (t >= 270) return;
    int p = t / 30;
    double a1 = 0, a2 = 0;
    int b0 = blockIdx.x * 16;
    for (int bb = 0; bb < 16; bb++) {
        int b = b0 + bb;
        float cnt = g_hist[b];
        if (cnt == 0.f) continue;
        float m1 = g_hist[NB + b], m2 = g_hist[2 * NB + b];
        float dc = ((float)b + 0.5f) * (1.0f / (float)NB);
        float alpha = rb2[t], beta = 0.f;
#pragma unroll
        for (int u = 0; u < 10; u++) {
            float A = sA[p * 10 + u], Bv = sB[p * 10 + u];
            if (fmaf(A, dc, Bv) > 0.f) {
                float w = rW2[p * 300 + (t - p * 30) * 10 + u];
                alpha = fmaf(w, Bv, alpha);
                beta  = fmaf(w, A,  beta);
            }
        }
        double a = alpha, be = beta;
        a1 += a * (double)cnt + be * (double)m1;
        a2 += a * a * (double)cnt + 2.0 * a * be * (double)m1 + be * be * (double)m2;
    }
    atomicAdd(&g_stats[2 * t],     a1);
    atomicAdd(&g_stats[2 * t + 1], a2);
}

// ---- launch 2: BN2 fold + LUT rows -----------------------------------------
__global__ void k_lutbn2(const float* __restrict__ rg2, const float* __restrict__ rbb2,
                         const float* __restrict__ rW2, const float* __restrict__ rb2,
                         const float* __restrict__ rW3, const float* __restrict__ rb3,
                         int E) {
    __shared__ float sc[270], sh[270], h1[90], h2[272];
    int t = threadIdx.x;
    if (t < 270) {
        double mean = g_stats[2 * t] / (double)E;
        double var  = g_stats[2 * t + 1] / (double)E - mean * mean;
        if (var < 0) var = 0;
        float s = rg2[t] * rsqrtf((float)var + EPSV);
        sc[t] = s;
        sh[t] = rbb2[t] - (float)mean * s;
    }
    float d = (float)blockIdx.x * (1.0f / (float)NLUT);
    if (t < 90) h1[t] = fmaxf(0.f, fmaf(g_AB[t], d, g_AB[90 + t]));
    __syncthreads();
    if (t < 270) {
        int p = t / 30;
        float z = rb2[t];
#pragma unroll
        for (int u = 0; u < 10; u++)
            z = fmaf(rW2[p * 300 + (t - p * 30) * 10 + u], h1[p * 10 + u], z);
        h2[t] = fmaxf(0.f, fmaf(z, sc[t], sh[t]));
    }
    __syncthreads();
    if (t < 80) {
        float R = 0.f;
        if (t < 76) {
            int p = 0;
#pragma unroll
            for (int pp = 1; pp < 9; pp++) if (t >= c_Roff4[pp]) p = pp;
            int r = t - c_Roff4[p];
            R = rb3[p * 20 + r];
#pragma unroll
            for (int v = 0; v < 30; v++)
                R = fmaf(rW3[p * 600 + r * 30 + v], h2[p * 30 + v], R);
        }
        size_t b = blockIdx.x;
        g_lut2[(b * 80 + t) * 2] = R;
        if (b > 0) g_lut2[((b - 1) * 80 + t) * 2 + 1] = R;
    }
}

// ---- launch 3: main kernel (lean-L1 body, 3 CTAs/SM) ------------------------
// per-warp smem (2 x 256 floats): R[0..76) | qi[76..94) | fi[94..112) | B[112..250)
__global__ void __launch_bounds__(256, 3) k_main(
    const int* __restrict__ dst, const float* __restrict__ dist,
    const float* __restrict__ wa0, const float* __restrict__ wa1,
    const float* __restrict__ wa2, const float* __restrict__ wa3,
    const float* __restrict__ wa4, const float* __restrict__ wa5,
    const float* __restrict__ wa6, const float* __restrict__ wa7,
    const float* __restrict__ wa8,
    float* __restrict__ eout, int E) {
    __shared__ __align__(16) float S[8 * 512];
    int lane = threadIdx.x & 31;
    float* s0 = S + ((threadIdx.x >> 5) << 9);
    float* s1 = s0 + 256;

    const float* wb[9] = {wa0, wa1, wa2, wa3, wa4, wa5, wa6, wa7, wa8};

    int gw = (int)((blockIdx.x * blockDim.x + threadIdx.x) >> 5);
    int nw = (int)((gridDim.x * blockDim.x) >> 5);
    int nw2 = 2 * nw;

    // per-lane register tables, packed for register economy
    const float* sp[9];                 // 18 regs (needed: distinct array bases)
    unsigned sstrp0, sstrp1, sstrp2;    // sstr[9] packed 4x u8 per reg
    unsigned sbq2[5];                   // 9 slots x 16 bits: [sb:8 | sq:8]
    {
        unsigned tmp[9], str[9];
#pragma unroll
        for (int it = 0; it < 9; it++) {
            uchar4 c = g_ct[it * 32 + lane];
            int sz   = c_SZ[c.x];
            sp[it]   = wb[c.x] + (int)c.y + 2 * gw * sz;
            str[it]  = (unsigned)sz;
            tmp[it]  = ((unsigned)c.z * 2) | (((unsigned)c.w * 2) << 8);
        }
        sstrp0 = str[0] | (str[1] << 8) | (str[2] << 16) | (str[3] << 24);
        sstrp1 = str[4] | (str[5] << 8) | (str[6] << 16) | (str[7] << 24);
        sstrp2 = str[8];
#pragma unroll
        for (int i = 0; i < 4; i++) sbq2[i] = tmp[2 * i] | (tmp[2 * i + 1] << 16);
        sbq2[4] = tmp[8];
    }
    int bq[3];                          // quad*4 | (fpos*2 << 8) | (pair*2 << 16)
#pragma unroll
    for (int it = 0; it < 3; it++) {
        uchar4 c = g_bt[it * 32 + lane];
        bq[it] = ((int)c.x * 4) | (((int)c.y * 2) << 8) | (((int)c.z * 2) << 16);
    }

#define SSTR(it) ((it) < 4 ? ((sstrp0 >> (8 * (it))) & 0xFFu) \
                 : (it) < 8 ? ((sstrp1 >> (8 * ((it) - 4))) & 0xFFu) : sstrp2)
#define SBQF(it) (((sbq2[(it) >> 1] >> (16 * ((it) & 1))) & 0xFFFFu))

    int e0 = 2 * gw;
    int   nd0n = 0, nd1n = 0;
    float d0n = 0.f, d1n = 0.f;
    if (e0 < E) {
        if (e0 + 1 < E) {
            int2 jj = *(const int2*)(dst + e0);
            float2 dd = *(const float2*)(dist + e0);
            nd0n = jj.x; nd1n = jj.y; d0n = dd.x; d1n = dd.y;
        } else {
            nd0n = dst[e0]; d0n = dist[e0]; nd1n = nd0n; d1n = d0n;
        }
    }

    for (; e0 < E; e0 += nw2) {
        bool v1 = (e0 + 1 < E);
        int   nd0 = nd0n, nd1 = nd1n;
        float d0 = d0n, d1 = d1n;

        // ---- 1. issue all wj loads first
        float w0[9], w1[9];
#pragma unroll
        for (int it = 0; it < 9; it++) {
            unsigned sz = SSTR(it);
            w0[it] = __ldcs(sp[it]);
            w1[it] = v1 ? __ldcs(sp[it] + sz) : 0.f;
            sp[it] += sz * (unsigned)nw2;
        }

        // ---- 2a. node loads -> commit immediately (short live range)
        if (lane < 9) {
            float4 nA = *(const float4*)(g_node + (size_t)nd0 * 40 + 4 * lane);
            float4 nB = *(const float4*)(g_node + (size_t)nd1 * 40 + 4 * lane);
            *(float4*)(s0 + 76 + 4 * lane) = nA;
            *(float4*)(s1 + 76 + 4 * lane) = nB;
        }

        // ---- 2b. LUT loads -> interp -> commit
        {
            float td0 = d0 * (float)NLUT;
            int i00 = max(0, min(NLUT - 1, (int)td0));
            float fr0 = td0 - (float)i00;
            float td1 = d1 * (float)NLUT;
            int i01 = max(0, min(NLUT - 1, (int)td1));
            float fr1 = td1 - (float)i01;
            const float4* L0 = (const float4*)(g_lut2 + (size_t)i00 * 160);
            const float4* L1 = (const float4*)(g_lut2 + (size_t)i01 * 160);
            float4 la0 = L0[lane], lb0 = L1[lane];
            *(float2*)(s0 + 2 * lane) =
                make_float2(fmaf(fr0, la0.y - la0.x, la0.x), fmaf(fr0, la0.w - la0.z, la0.z));
            *(float2*)(s1 + 2 * lane) =
                make_float2(fmaf(fr1, lb0.y - lb0.x, lb0.x), fmaf(fr1, lb0.w - lb0.z, lb0.z));
            if (lane < 6) {
                float4 la1 = L0[32 + lane], lb1 = L1[32 + lane];
                *(float2*)(s0 + 64 + 2 * lane) =
                    make_float2(fmaf(fr0, la1.y - la1.x, la1.x), fmaf(fr0, la1.w - la1.z, la1.z));
                *(float2*)(s1 + 64 + 2 * lane) =
                    make_float2(fmaf(fr1, lb1.y - lb1.x, lb1.x), fmaf(fr1, lb1.w - lb1.z, lb1.z));
            }
        }

        // ---- 3. prefetch next iteration's dst/dist (vectorized)
        {
            int en = e0 + nw2;
            if (en < E) {
                if (en + 1 < E) {
                    int2 jj = *(const int2*)(dst + en);
                    float2 dd = *(const float2*)(dist + en);
                    nd0n = jj.x; nd1n = jj.y; d0n = dd.x; d1n = dd.y;
                } else {
                    nd0n = dst[en]; d0n = dist[en]; nd1n = nd0n; d1n = d0n;
                }
            }
        }
        __syncwarp();

        // ---- 4. B build (69 slots, guard it<2 || lane<5)
#pragma unroll
        for (int it = 0; it < 3; it++) {
            if (it < 2 || lane < 5) {
                int quad = bq[it] & 0xFF, fp = (bq[it] >> 8) & 0xFF, pr = bq[it] >> 16;
                float4 Ra = *(const float4*)(s0 + quad);
                float2 fa = *(const float2*)(s0 + 94 + fp);
                *(float2*)(s0 + 112 + pr) =
                    make_float2(Ra.x * fa.x + Ra.y * fa.y, Ra.z * fa.x + Ra.w * fa.y);
                float4 Rb = *(const float4*)(s1 + quad);
                float2 fb = *(const float2*)(s1 + 94 + fp);
                *(float2*)(s1 + 112 + pr) =
                    make_float2(Rb.x * fb.x + Rb.y * fb.y, Rb.z * fb.x + Rb.w * fb.y);
            }
        }
        __syncwarp();

        // ---- 5. contraction (259 slots, guard it<8 || lane<3)
        float acc0 = 0.f, acc1 = 0.f;
#pragma unroll
        for (int it = 0; it < 9; it++) {
            bool valid = (it < 8) || (lane < 3);
            float wv0 = valid ? w0[it] : 0.f;
            float wv1 = valid ? w1[it] : 0.f;
            unsigned f = SBQF(it);
            int sb = (int)(f & 0xFFu), sq = (int)(f >> 8);
            float2 b0 = *(const float2*)(s0 + 112 + sb);
            float2 q0 = *(const float2*)(s0 + 76 + sq);
            acc0 = fmaf(wv0, fmaf(q0.x, b0.x, q0.y * b0.y), acc0);
            float2 b1 = *(const float2*)(s1 + 112 + sb);
            float2 q1 = *(const float2*)(s1 + 76 + sq);
            acc1 = fmaf(wv1, fmaf(q1.x, b1.x, q1.y * b1.y), acc1);
        }
#pragma unroll
        for (int o = 16; o > 0; o >>= 1) {
            acc0 += __shfl_xor_sync(0xFFFFFFFFu, acc0, o);
            acc1 += __shfl_xor_sync(0xFFFFFFFFu, acc1, o);
        }

        if (lane == 0) {
            float ev0 = expf(acc0);
            eout[e0] = ev0;
            atomicAdd(&g_s[nd0], ev0);
        }
        if (lane == 1 && v1) {
            float ev1 = expf(acc1);
            eout[e0 + 1] = ev1;
            atomicAdd(&g_s[nd1], ev1);
        }
        __syncwarp();
    }
#undef SSTR
#undef SBQF
}

// ---- launch 4: normalize ----------------------------------------------------
__global__ void k_div(const int* __restrict__ dst, float* __restrict__ out, int E) {
    int e = blockIdx.x * blockDim.x + threadIdx.x;
    if (e < E) out[e] = out[e] / g_s[dst[e]];
}

// ---------------------------------------------------------------------------
extern "C" void kernel_launch(void* const* d_in, const int* in_sizes, int n_in,
                              void* d_out, int out_size) {
    int b = (n_in == 26) ? 1 : 0;
    const int*   dst  = (const int*)d_in[b + 0];
    const float* dist = (const float*)d_in[b + 1];
    const float* f0   = (const float*)d_in[b + 2];
    const float* f1   = (const float*)d_in[b + 3];
    const float* f2   = (const float*)d_in[b + 4];
    const float* wq   = (const float*)d_in[b + 5];
    const float* wj[9];
    for (int i = 0; i < 9; i++) wj[i] = (const float*)d_in[b + 6 + i];  // a = k*3+l
    const float* rW1  = (const float*)d_in[b + 15];
    const float* rg1  = (const float*)d_in[b + 17];
    const float* rbb1 = (const float*)d_in[b + 18];
    const float* rW2  = (const float*)d_in[b + 19];
    const float* rb2  = (const float*)d_in[b + 20];
    const float* rg2  = (const float*)d_in[b + 21];
    const float* rbb2 = (const float*)d_in[b + 22];
    const float* rW3  = (const float*)d_in[b + 23];
    const float* rb3  = (const float*)d_in[b + 24];

    int E = in_sizes[b + 0];
    int N = in_sizes[b + 2] / 2;
    float* out = (float*)d_out;

    void *p_hist = nullptr, *p_s = nullptr, *p_stats = nullptr;
    cudaGetSymbolAddress(&p_hist, g_hist);
    cudaGetSymbolAddress(&p_s, g_s);
    cudaGetSymbolAddress(&p_stats, g_stats);
    cudaMemsetAsync(p_hist, 0, sizeof(float) * 3 * NB);
    cudaMemsetAsync(p_s, 0, sizeof(float) * NMAX);
    cudaMemsetAsync(p_stats, 0, sizeof(double) * 540);

    k_fused0<<<296, 256>>>(f0, f1, f2, wq, dist, N, E);            // launch 0
    k_statsAB<<<NB / 16, 288>>>(rW1, rg1, rbb1, rW2, rb2, E);      // launch 1
    k_lutbn2<<<NLUT + 1, 288>>>(rg2, rbb2, rW2, rb2, rW3, rb3, E); // launch 2
    k_main<<<444, 256>>>(dst, dist,                                 // launch 3 (profiled)
                         wj[0], wj[1], wj[2],
                         wj[3], wj[4], wj[5],
                         wj[6], wj[7], wj[8],
                         out, E);
    k_div<<<(E + 255) / 256, 256>>>(dst, out, E);                  // launch 4
}

// round 15
// speedup vs baseline: 1.0448x; 1.0448x over previous
#include <cuda_runtime.h>
#include <math.h>
#include <stdint.h>

// ============================================================================
// AttnBlock: SE(3)-attention edge softmax, D=2, C=2.
//  - radial MLP -> 2048-pt LUT (BN stats exact via moment histogram).
//  - fused aux chain (3 kernels, ~33us) + R7 two-stage-pipeline k_main (best
//    passing main body, 469us total with slow aux). k_main = launch index 3.
// ============================================================================

#define NB     2048
#define NLUT   2048
#define NMAX   50048
#define EPSV   1e-5f

__device__ float  g_hist[3 * NB];
__device__ float  g_AB[180];
__device__ double g_stats[540];
__device__ float  g_lut2[(size_t)(NLUT + 1) * 160];  // [i0][entry<80][{r_i0, r_i0+1}]
__device__ float  g_node[(size_t)NMAX * 36];         // qi[18] | fi[18] (R7 layout)
__device__ float  g_s[NMAX];
__device__ uchar4 g_ct[288];   // contraction slot -> (arr, off, b2pair, qpair)
__device__ uchar4 g_bt[96];    // build slot -> (quad, fpos, pair, 0)

__constant__ int c_Roff4[9] = {0, 4, 8, 12, 16, 28, 40, 44, 56}; // p = l*3+k
__constant__ int c_SZ[9]    = {1, 3, 5, 3, 27, 45, 5, 45, 125};  // a = k*3+l

// ---- launch 0: tables + node transform + histogram -------------------------
__global__ void k_fused0(const float* __restrict__ f0, const float* __restrict__ f1,
                         const float* __restrict__ f2, const float* __restrict__ wq,
                         const float* __restrict__ dist, int N, int E) {
    if (blockIdx.x == 0 && threadIdx.x == 0) {
        const int LOFF2[3] = {0, 1, 4};
        const int FOFF2[3] = {0, 1, 4};
        int PB[9]; int pb = 0;
        for (int a = 0; a < 9; a++) {
            int k = a / 3, l = a % 3;
            int J = 2 * min(k, l) + 1, K2 = 2 * k + 1;
            PB[a] = pb; pb += J * K2;
        }
        // contraction table: 259 entries canonical order + zero padding
        int flat = 0;
        for (int a = 0; a < 9; a++) {
            int k = a / 3, l = a % 3;
            int J = 2 * min(k, l) + 1, K2 = 2 * k + 1, L2 = 2 * l + 1;
            int SZ = J * L2 * K2;
            for (int t = 0; t < SZ; t++) {
                int mk = t % K2, r = t / K2, ml = r % L2, j = r / L2;
                uchar4 c;
                c.x = (unsigned char)a;
                c.y = (unsigned char)t;
                c.z = (unsigned char)(PB[a] + j * K2 + mk);
                c.w = (unsigned char)(LOFF2[l] + ml);
                g_ct[flat++] = c;
            }
        }
        for (; flat < 288; flat++) g_ct[flat] = make_uchar4(0, 0, 0, 0);
        // build table: 69 entries + zero padding
        int s = 0;
        for (int a = 0; a < 9; a++) {
            int k = a / 3, l = a % 3;
            int J = 2 * min(k, l) + 1, K2 = 2 * k + 1;
            int p_lk = l * 3 + k;
            int quadbase = c_Roff4[p_lk] / 4;
            for (int j = 0; j < J; j++)
                for (int mk = 0; mk < K2; mk++) {
                    uchar4 c;
                    c.x = (unsigned char)(quadbase + j);
                    c.y = (unsigned char)(FOFF2[k] + mk);
                    c.z = (unsigned char)(PB[a] + j * K2 + mk);
                    c.w = 0;
                    g_bt[s++] = c;
                }
        }
        for (; s < 96; s++) g_bt[s] = make_uchar4(0, 0, 0, 0);
    }

    // node transform (stride 36, R7 interleaved-pair layout)
    int n = blockIdx.x * blockDim.x + threadIdx.x;
    if (n < N) {
        const float* F0 = f0 + (size_t)n * 2;
        const float* F1 = f1 + (size_t)n * 6;
        const float* F2 = f2 + (size_t)n * 10;
        float* o_ = g_node + (size_t)n * 36;
#pragma unroll
        for (int o = 0; o < 2; o++) {
            o_[2 * 0 + o] = wq[0 + o * 2 + 0] * F0[0] + wq[0 + o * 2 + 1] * F0[1];
#pragma unroll
            for (int m = 0; m < 3; m++)
                o_[2 * (1 + m) + o] = wq[4 + o * 2 + 0] * F1[m] + wq[4 + o * 2 + 1] * F1[3 + m];
#pragma unroll
            for (int m = 0; m < 5; m++)
                o_[2 * (4 + m) + o] = wq[8 + o * 2 + 0] * F2[m] + wq[8 + o * 2 + 1] * F2[5 + m];
        }
        float* fo = o_ + 18;
#pragma unroll
        for (int i = 0; i < 2; i++) fo[2 * 0 + i] = F0[i];
#pragma unroll
        for (int m = 0; m < 3; m++)
#pragma unroll
            for (int i = 0; i < 2; i++) fo[2 * (1 + m) + i] = F1[i * 3 + m];
#pragma unroll
        for (int m = 0; m < 5; m++)
#pragma unroll
            for (int i = 0; i < 2; i++) fo[2 * (4 + m) + i] = F2[i * 5 + m];
    }

    // histogram
    __shared__ float h[3 * NB];
    for (int i = threadIdx.x; i < 3 * NB; i += blockDim.x) h[i] = 0.f;
    __syncthreads();
    int i0 = blockIdx.x * blockDim.x + threadIdx.x, st = gridDim.x * blockDim.x;
    for (int e = i0; e < E; e += st) {
        float d = dist[e];
        int b = (int)(d * (float)NB);
        b = max(0, min(NB - 1, b));
        atomicAdd(&h[b], 1.f);
        atomicAdd(&h[NB + b], d);
        atomicAdd(&h[2 * NB + b], d * d);
    }
    __syncthreads();
    for (int j = threadIdx.x; j < 3 * NB; j += blockDim.x)
        if (h[j] != 0.f) atomicAdd(&g_hist[j], h[j]);
}

// ---- launch 1: dist mean/var + L1 affines + L2 stats slice -----------------
__global__ void k_statsAB(const float* __restrict__ rW1, const float* __restrict__ rg1,
                          const float* __restrict__ rbb1, const float* __restrict__ rW2,
                          const float* __restrict__ rb2, int E) {
    __shared__ double rs[3 * 288];
    __shared__ float sA[90], sB[90];
    __shared__ float smu, svar;
    int t = threadIdx.x;
    double c = 0, s1 = 0, s2 = 0;
    for (int b = t; b < NB; b += 288) {
        c  += (double)g_hist[b];
        s1 += (double)g_hist[NB + b];
        s2 += (double)g_hist[2 * NB + b];
    }
    rs[t] = c; rs[288 + t] = s1; rs[576 + t] = s2;
    __syncthreads();
    if (t == 0) {
        double t1 = 0, t2 = 0;
        for (int i = 0; i < 288; i++) { t1 += rs[288 + i]; t2 += rs[576 + i]; }
        double mu  = t1 / (double)E;
        double var = t2 / (double)E - mu * mu;
        if (var < 0) var = 0;
        smu = (float)mu; svar = (float)var;
    }
    __syncthreads();
    if (t < 90) {
        float w = rW1[t], gi = rg1[t];
        float inv = rsqrtf(svar * w * w + EPSV);
        sA[t] = w * gi * inv;
        sB[t] = rbb1[t] - w * smu * gi * inv;
        if (blockIdx.x == 0) { g_AB[t] = sA[t]; g_AB[90 + t] = sB[t]; }
    }
    __syncthreads();
    if (t >= 270) return;
    int p = t / 30;
    double a1 = 0, a2 = 0;
    int b0 = blockIdx.x * 16;
    for (int bb = 0; bb < 16; bb++) {
        int b = b0 + bb;
        float cnt = g_hist[b];
        if (cnt == 0.f) continue;
        float m1 = g_hist[NB + b], m2 = g_hist[2 * NB + b];
        float dc = ((float)b + 0.5f) * (1.0f / (float)NB);
        float alpha = rb2[t], beta = 0.f;
#pragma unroll
        for (int u = 0; u < 10; u++) {
            float A = sA[p * 10 + u], Bv = sB[p * 10 + u];
            if (fmaf(A, dc, Bv) > 0.f) {
                float w = rW2[p * 300 + (t - p * 30) * 10 + u];
                alpha = fmaf(w, Bv, alpha);
                beta  = fmaf(w, A,  beta);
            }
        }
        double a = alpha, be = beta;
        a1 += a * (double)cnt + be * (double)m1;
        a2 += a * a * (double)cnt + 2.0 * a * be * (double)m1 + be * be * (double)m2;
    }
    atomicAdd(&g_stats[2 * t],     a1);
    atomicAdd(&g_stats[2 * t + 1], a2);
}

// ---- launch 2: BN2 fold + LUT rows -----------------------------------------
__global__ void k_lutbn2(const float* __restrict__ rg2, const float* __restrict__ rbb2,
                         const float* __restrict__ rW2, const float* __restrict__ rb2,
                         const float* __restrict__ rW3, const float* __restrict__ rb3,
                         int E) {
    __shared__ float sc[270], sh[270], h1[90], h2[272];
    int t = threadIdx.x;
    if (t < 270) {
        double mean = g_stats[2 * t] / (double)E;
        double var  = g_stats[2 * t + 1] / (double)E - mean * mean;
        if (var < 0) var = 0;
        float s = rg2[t] * rsqrtf((float)var + EPSV);
        sc[t] = s;
        sh[t] = rbb2[t] - (float)mean * s;
    }
    float d = (float)blockIdx.x * (1.0f / (float)NLUT);
    if (t < 90) h1[t] = fmaxf(0.f, fmaf(g_AB[t], d, g_AB[90 + t]));
    __syncthreads();
    if (t < 270) {
        int p = t / 30;
        float z = rb2[t];
#pragma unroll
        for (int u = 0; u < 10; u++)
            z = fmaf(rW2[p * 300 + (t - p * 30) * 10 + u], h1[p * 10 + u], z);
        h2[t] = fmaxf(0.f, fmaf(z, sc[t], sh[t]));
    }
    __syncthreads();
    if (t < 80) {
        float R = 0.f;
        if (t < 76) {
            int p = 0;
#pragma unroll
            for (int pp = 1; pp < 9; pp++) if (t >= c_Roff4[pp]) p = pp;
            int r = t - c_Roff4[p];
            R = rb3[p * 20 + r];
#pragma unroll
            for (int v = 0; v < 30; v++)
                R = fmaf(rW3[p * 600 + r * 30 + v], h2[p * 30 + v], R);
        }
        size_t b = blockIdx.x;
        g_lut2[(b * 80 + t) * 2] = R;
        if (b > 0) g_lut2[((b - 1) * 80 + t) * 2 + 1] = R;
    }
}

// ---- launch 3: main kernel (R7 two-stage pipeline body, verbatim) ----------
// per warp: 2 stages x 2 edges x 256 floats.
//   buf: R[0..76) | qi[76..94) | fi[94..112) | B2[112..250)
__global__ void __launch_bounds__(256, 2) k_main(
    const int* __restrict__ dst, const float* __restrict__ dist,
    const float* __restrict__ wa0, const float* __restrict__ wa1,
    const float* __restrict__ wa2, const float* __restrict__ wa3,
    const float* __restrict__ wa4, const float* __restrict__ wa5,
    const float* __restrict__ wa6, const float* __restrict__ wa7,
    const float* __restrict__ wa8,
    float* __restrict__ eout, int E) {
    __shared__ __align__(16) float S[8 * 1024];
    int lane = threadIdx.x & 31;
    float* base = S + ((threadIdx.x >> 5) << 10);

    const float* wb[9] = {wa0, wa1, wa2, wa3, wa4, wa5, wa6, wa7, wa8};

    int gw = (int)((blockIdx.x * blockDim.x + threadIdx.x) >> 5);
    int nw = (int)((gridDim.x * blockDim.x) >> 5);
    int nw2 = 2 * nw;

    const float* sp[9];
    int sstr[9], sb_[9], sq_[9];
#pragma unroll
    for (int it = 0; it < 9; it++) {
        uchar4 c = g_ct[it * 32 + lane];
        int sz   = c_SZ[c.x];
        sp[it]   = wb[c.x] + (int)c.y + 2 * gw * sz;
        sstr[it] = sz;
        sb_[it]  = (int)c.z * 2;
        sq_[it]  = (int)c.w * 2;
    }
    int bquad[3], bfp[3], bpr[3];
#pragma unroll
    for (int it = 0; it < 3; it++) {
        uchar4 c = g_bt[it * 32 + lane];
        bquad[it] = (int)c.x * 4;
        bfp[it]   = (int)c.y * 2;
        bpr[it]   = (int)c.z * 2;
    }

    int e = 2 * gw;
    if (e >= E) return;

    // dst/dist for iter 0 (A) and iter 1 (B)
    int   ndA0 = dst[e];
    float dA0  = dist[e];
    bool  vA   = (e + 1 < E);
    int   ndA1 = vA ? dst[e + 1] : ndA0;
    float dA1  = vA ? dist[e + 1] : dA0;
    int   ndB0 = 0, ndB1 = 0;
    float dB0 = 0.f, dB1 = 0.f;
    {
        int en = e + nw2;
        if (en < E) {
            ndB0 = dst[en];
            dB0  = dist[en];
            bool v = (en + 1 < E);
            ndB1 = v ? dst[en + 1] : ndB0;
            dB1  = v ? dist[en + 1] : dB0;
        }
    }

    // prologue: fill stage 0 with iter-0 node+LUT
    {
        float* s0 = base;
        float* s1 = base + 256;
        const float* np0 = g_node + (size_t)ndA0 * 36;
        const float* np1 = g_node + (size_t)ndA1 * 36;
        s0[76 + lane] = np0[lane];
        s1[76 + lane] = np1[lane];
        if (lane < 4) { s0[108 + lane] = np0[32 + lane]; s1[108 + lane] = np1[32 + lane]; }
        float td0 = dA0 * (float)NLUT;
        int i00 = max(0, min(NLUT - 1, (int)td0));
        float fr0 = td0 - (float)i00;
        float td1 = dA1 * (float)NLUT;
        int i01 = max(0, min(NLUT - 1, (int)td1));
        float fr1 = td1 - (float)i01;
        const float2* Lp0 = (const float2*)g_lut2 + (size_t)i00 * 80;
        const float2* Lp1 = (const float2*)g_lut2 + (size_t)i01 * 80;
#pragma unroll
        for (int it = 0; it < 3; it++) {
            int i = it * 32 + lane;
            if (it < 2 || lane < 12) {
                float2 ra = Lp0[i], rb = Lp1[i];
                s0[i] = fmaf(fr0, ra.y - ra.x, ra.x);
                s1[i] = fmaf(fr1, rb.y - rb.x, rb.x);
            }
        }
    }

    int p = 0;
    for (; e < E; e += nw2, p ^= 1) {
        float* s0 = base + (p << 9);
        float* s1 = s0 + 256;
        float* t0 = base + ((p ^ 1) << 9);
        float* t1 = t0 + 256;
        bool v1 = (e + 1 < E);

        // ---- 1. wj loads for THIS iteration (covered by compute below)
        float w0[9], w1[9];
#pragma unroll
        for (int it = 0; it < 9; it++) {
            w0[it] = __ldcs(sp[it]);
            w1[it] = v1 ? __ldcs(sp[it] + sstr[it]) : 0.f;
            sp[it] += sstr[it] * nw2;
        }

        // ---- 2. issue node+LUT loads for NEXT iteration
        const float* np0 = g_node + (size_t)ndB0 * 36;
        const float* np1 = g_node + (size_t)ndB1 * 36;
        float nq0 = np0[lane], nq1 = np1[lane];
        float nx0 = 0.f, nx1 = 0.f;
        if (lane < 4) { nx0 = np0[32 + lane]; nx1 = np1[32 + lane]; }
        float tdb0 = dB0 * (float)NLUT;
        int ib0 = max(0, min(NLUT - 1, (int)tdb0));
        float frb0 = tdb0 - (float)ib0;
        float tdb1 = dB1 * (float)NLUT;
        int ib1 = max(0, min(NLUT - 1, (int)tdb1));
        float frb1 = tdb1 - (float)ib1;
        const float2* LpB0 = (const float2*)g_lut2 + (size_t)ib0 * 80;
        const float2* LpB1 = (const float2*)g_lut2 + (size_t)ib1 * 80;
        float2 ra[3], rb[3];
#pragma unroll
        for (int it = 0; it < 3; it++) {
            int i = it * 32 + lane;
            if (it < 2 || lane < 12) { ra[it] = LpB0[i]; rb[it] = LpB1[i]; }
        }

        // ---- 3. prefetch dst/dist two iterations ahead
        int   ndC0 = 0, ndC1 = 0;
        float dC0 = 0.f, dC1 = 0.f;
        {
            int e2 = e + 2 * nw2;
            if (e2 < E) {
                ndC0 = dst[e2];
                dC0  = dist[e2];
                bool v = (e2 + 1 < E);
                ndC1 = v ? dst[e2 + 1] : ndC0;
                dC1  = v ? dist[e2 + 1] : dC0;
            }
        }

        // ---- 4. sync: stage-p buffers (committed last iteration) are ready
        __syncwarp();

        // ---- 5a. B build in stage p
#pragma unroll
        for (int it = 0; it < 3; it++) {
            if (it < 2 || lane < 5) {
                float4 Ra = *(const float4*)(s0 + bquad[it]);
                float2 fa = *(const float2*)(s0 + 94 + bfp[it]);
                *(float2*)(s0 + 112 + bpr[it]) =
                    make_float2(Ra.x * fa.x + Ra.y * fa.y, Ra.z * fa.x + Ra.w * fa.y);
                float4 Rb = *(const float4*)(s1 + bquad[it]);
                float2 fb = *(const float2*)(s1 + 94 + bfp[it]);
                *(float2*)(s1 + 112 + bpr[it]) =
                    make_float2(Rb.x * fb.x + Rb.y * fb.y, Rb.z * fb.x + Rb.w * fb.y);
            }
        }
        __syncwarp();

        // ---- 5b. contraction + reduce + output
        float acc0 = 0.f, acc1 = 0.f;
#pragma unroll
        for (int it = 0; it < 9; it++) {
            bool valid = (it < 8) || (lane < 3);   // 259 = 8*32+3
            float wv0 = valid ? w0[it] : 0.f;
            float wv1 = valid ? w1[it] : 0.f;
            float2 b0 = *(const float2*)(s0 + 112 + sb_[it]);
            float2 q0 = *(const float2*)(s0 + 76 + sq_[it]);
            acc0 = fmaf(wv0, fmaf(q0.x, b0.x, q0.y * b0.y), acc0);
            float2 b1 = *(const float2*)(s1 + 112 + sb_[it]);
            float2 q1 = *(const float2*)(s1 + 76 + sq_[it]);
            acc1 = fmaf(wv1, fmaf(q1.x, b1.x, q1.y * b1.y), acc1);
        }
#pragma unroll
        for (int o = 16; o > 0; o >>= 1) {
            acc0 += __shfl_xor_sync(0xFFFFFFFFu, acc0, o);
            acc1 += __shfl_xor_sync(0xFFFFFFFFu, acc1, o);
        }
        if (lane == 0) {
            float ev0 = expf(acc0);
            eout[e] = ev0;
            atomicAdd(&g_s[ndA0], ev0);
        }
        if (lane == 1 && v1) {
            float ev1 = expf(acc1);
            eout[e + 1] = ev1;
            atomicAdd(&g_s[ndA1], ev1);
        }

        // ---- 6. commit next iteration's node+LUT into stage p^1
        t0[76 + lane] = nq0;
        t1[76 + lane] = nq1;
        if (lane < 4) { t0[108 + lane] = nx0; t1[108 + lane] = nx1; }
#pragma unroll
        for (int it = 0; it < 3; it++) {
            int i = it * 32 + lane;
            if (it < 2 || lane < 12) {
                t0[i] = fmaf(frb0, ra[it].y - ra[it].x, ra[it].x);
                t1[i] = fmaf(frb1, rb[it].y - rb[it].x, rb[it].x);
            }
        }

        // ---- 7. rotate edge metadata
        ndA0 = ndB0; ndA1 = ndB1; dA0 = dB0; dA1 = dB1;
        ndB0 = ndC0; ndB1 = ndC1; dB0 = dC0; dB1 = dC1;
    }
}

// ---- launch 4: normalize ----------------------------------------------------
__global__ void k_div(const int* __restrict__ dst, float* __restrict__ out, int E) {
    int e = blockIdx.x * blockDim.x + threadIdx.x;
    if (e < E) out[e] = out[e] / g_s[dst[e]];
}

// ---------------------------------------------------------------------------
extern "C" void kernel_launch(void* const* d_in, const int* in_sizes, int n_in,
                              void* d_out, int out_size) {
    int b = (n_in == 26) ? 1 : 0;
    const int*   dst  = (const int*)d_in[b + 0];
    const float* dist = (const float*)d_in[b + 1];
    const float* f0   = (const float*)d_in[b + 2];
    const float* f1   = (const float*)d_in[b + 3];
    const float* f2   = (const float*)d_in[b + 4];
    const float* wq   = (const float*)d_in[b + 5];
    const float* wj[9];
    for (int i = 0; i < 9; i++) wj[i] = (const float*)d_in[b + 6 + i];  // a = k*3+l
    const float* rW1  = (const float*)d_in[b + 15];
    const float* rg1  = (const float*)d_in[b + 17];
    const float* rbb1 = (const float*)d_in[b + 18];
    const float* rW2  = (const float*)d_in[b + 19];
    const float* rb2  = (const float*)d_in[b + 20];
    const float* rg2  = (const float*)d_in[b + 21];
    const float* rbb2 = (const float*)d_in[b + 22];
    const float* rW3  = (const float*)d_in[b + 23];
    const float* rb3  = (const float*)d_in[b + 24];

    int E = in_sizes[b + 0];
    int N = in_sizes[b + 2] / 2;
    float* out = (float*)d_out;

    void *p_hist = nullptr, *p_s = nullptr, *p_stats = nullptr;
    cudaGetSymbolAddress(&p_hist, g_hist);
    cudaGetSymbolAddress(&p_s, g_s);
    cudaGetSymbolAddress(&p_stats, g_stats);
    cudaMemsetAsync(p_hist, 0, sizeof(float) * 3 * NB);
    cudaMemsetAsync(p_s, 0, sizeof(float) * NMAX);
    cudaMemsetAsync(p_stats, 0, sizeof(double) * 540);

    k_fused0<<<296, 256>>>(f0, f1, f2, wq, dist, N, E);            // launch 0
    k_statsAB<<<NB / 16, 288>>>(rW1, rg1, rbb1, rW2, rb2, E);      // launch 1
    k_lutbn2<<<NLUT + 1, 288>>>(rg2, rbb2, rW2, rb2, rW3, rb3, E); // launch 2
    k_main<<<296, 256>>>(dst, dist,                                 // launch 3 (profiled)
                         wj[0], wj[1], wj[2],
                         wj[3], wj[4], wj[5],
                         wj[6], wj[7], wj[8],
                         out, E);
    k_div<<<(E + 255) / 256, 256>>>(dst, out, E);                  // launch 4
}

// round 17
// speedup vs baseline: 1.0908x; 1.0440x over previous
#include <cuda_runtime.h>
#include <math.h>
#include <stdint.h>

// ============================================================================
// AttnBlock: SE(3)-attention edge softmax, D=2, C=2.
//  - radial MLP -> 1024-pt LUT (BN stats exact via moment histogram).
//  - fused aux chain with FLOAT BN2 fold (the per-block FP64 divisions in the
//    previous fused chain were a ~30-50us wall regression).
//  - k_main: R7/R15 two-stage-pipeline body verbatim (passed twice).
//    k_main = launch index 3 (ncu-profiled).
// ============================================================================

#define NB     2048
#define NLUT   1024
#define NMAX   50048
#define EPSV   1e-5f

__device__ float  g_hist[3 * NB];
__device__ float  g_AB[180];
__device__ double g_stats[540];
__device__ float  g_lut2[(size_t)(NLUT + 1) * 160];  // [i0][entry<80][{r_i0, r_i0+1}]
__device__ float  g_node[(size_t)NMAX * 36];         // qi[18] | fi[18]
__device__ float  g_s[NMAX];
__device__ uchar4 g_ct[288];   // contraction slot -> (arr, off, b2pair, qpair)
__device__ uchar4 g_bt[96];    // build slot -> (quad, fpos, pair, 0)

__constant__ int c_Roff4[9] = {0, 4, 8, 12, 16, 28, 40, 44, 56}; // p = l*3+k
__constant__ int c_SZ[9]    = {1, 3, 5, 3, 27, 45, 5, 45, 125};  // a = k*3+l

// ---- launch 0: tables + node transform + histogram -------------------------
__global__ void k_fused0(const float* __restrict__ f0, const float* __restrict__ f1,
                         const float* __restrict__ f2, const float* __restrict__ wq,
                         const float* __restrict__ dist, int N, int E) {
    if (blockIdx.x == 0 && threadIdx.x == 0) {
        const int LOFF2[3] = {0, 1, 4};
        const int FOFF2[3] = {0, 1, 4};
        int PB[9]; int pb = 0;
        for (int a = 0; a < 9; a++) {
            int k = a / 3, l = a % 3;
            int J = 2 * min(k, l) + 1, K2 = 2 * k + 1;
            PB[a] = pb; pb += J * K2;
        }
        int flat = 0;
        for (int a = 0; a < 9; a++) {
            int k = a / 3, l = a % 3;
            int J = 2 * min(k, l) + 1, K2 = 2 * k + 1, L2 = 2 * l + 1;
            int SZ = J * L2 * K2;
            for (int t = 0; t < SZ; t++) {
                int mk = t % K2, r = t / K2, ml = r % L2, j = r / L2;
                uchar4 c;
                c.x = (unsigned char)a;
                c.y = (unsigned char)t;
                c.z = (unsigned char)(PB[a] + j * K2 + mk);
                c.w = (unsigned char)(LOFF2[l] + ml);
                g_ct[flat++] = c;
            }
        }
        for (; flat < 288; flat++) g_ct[flat] = make_uchar4(0, 0, 0, 0);
        int s = 0;
        for (int a = 0; a < 9; a++) {
            int k = a / 3, l = a % 3;
            int J = 2 * min(k, l) + 1, K2 = 2 * k + 1;
            int p_lk = l * 3 + k;
            int quadbase = c_Roff4[p_lk] / 4;
            for (int j = 0; j < J; j++)
                for (int mk = 0; mk < K2; mk++) {
                    uchar4 c;
                    c.x = (unsigned char)(quadbase + j);
                    c.y = (unsigned char)(FOFF2[k] + mk);
                    c.z = (unsigned char)(PB[a] + j * K2 + mk);
                    c.w = 0;
                    g_bt[s++] = c;
                }
        }
        for (; s < 96; s++) g_bt[s] = make_uchar4(0, 0, 0, 0);
    }

    // node transform (stride 36, interleaved-pair layout)
    int n = blockIdx.x * blockDim.x + threadIdx.x;
    if (n < N) {
        const float* F0 = f0 + (size_t)n * 2;
        const float* F1 = f1 + (size_t)n * 6;
        const float* F2 = f2 + (size_t)n * 10;
        float* o_ = g_node + (size_t)n * 36;
#pragma unroll
        for (int o = 0; o < 2; o++) {
            o_[2 * 0 + o] = wq[0 + o * 2 + 0] * F0[0] + wq[0 + o * 2 + 1] * F0[1];
#pragma unroll
            for (int m = 0; m < 3; m++)
                o_[2 * (1 + m) + o] = wq[4 + o * 2 + 0] * F1[m] + wq[4 + o * 2 + 1] * F1[3 + m];
#pragma unroll
            for (int m = 0; m < 5; m++)
                o_[2 * (4 + m) + o] = wq[8 + o * 2 + 0] * F2[m] + wq[8 + o * 2 + 1] * F2[5 + m];
        }
        float* fo = o_ + 18;
#pragma unroll
        for (int i = 0; i < 2; i++) fo[2 * 0 + i] = F0[i];
#pragma unroll
        for (int m = 0; m < 3; m++)
#pragma unroll
            for (int i = 0; i < 2; i++) fo[2 * (1 + m) + i] = F1[i * 3 + m];
#pragma unroll
        for (int m = 0; m < 5; m++)
#pragma unroll
            for (int i = 0; i < 2; i++) fo[2 * (4 + m) + i] = F2[i * 5 + m];
    }

    // histogram
    __shared__ float h[3 * NB];
    for (int i = threadIdx.x; i < 3 * NB; i += blockDim.x) h[i] = 0.f;
    __syncthreads();
    int i0 = blockIdx.x * blockDim.x + threadIdx.x, st = gridDim.x * blockDim.x;
    for (int e = i0; e < E; e += st) {
        float d = dist[e];
        int b = (int)(d * (float)NB);
        b = max(0, min(NB - 1, b));
        atomicAdd(&h[b], 1.f);
        atomicAdd(&h[NB + b], d);
        atomicAdd(&h[2 * NB + b], d * d);
    }
    __syncthreads();
    for (int j = threadIdx.x; j < 3 * NB; j += blockDim.x)
        if (h[j] != 0.f) atomicAdd(&g_hist[j], h[j]);
}

// ---- launch 1: dist mean/var + L1 affines + L2 stats slice -----------------
__global__ void k_statsAB(const float* __restrict__ rW1, const float* __restrict__ rg1,
                          const float* __restrict__ rbb1, const float* __restrict__ rW2,
                          const float* __restrict__ rb2, int E) {
    __shared__ double rs[3 * 288];
    __shared__ float sA[90], sB[90];
    __shared__ float smu, svar;
    int t = threadIdx.x;
    double c = 0, s1 = 0, s2 = 0;
    for (int b = t; b < NB; b += 288) {
        c  += (double)g_hist[b];
        s1 += (double)g_hist[NB + b];
        s2 += (double)g_hist[2 * NB + b];
    }
    rs[t] = c; rs[288 + t] = s1; rs[576 + t] = s2;
    __syncthreads();
    if (t == 0) {
        double t1 = 0, t2 = 0;
        for (int i = 0; i < 288; i++) { t1 += rs[288 + i]; t2 += rs[576 + i]; }
        double mu  = t1 / (double)E;
        double var = t2 / (double)E - mu * mu;
        if (var < 0) var = 0;
        smu = (float)mu; svar = (float)var;
    }
    __syncthreads();
    if (t < 90) {
        float w = rW1[t], gi = rg1[t];
        float inv = rsqrtf(svar * w * w + EPSV);
        sA[t] = w * gi * inv;
        sB[t] = rbb1[t] - w * smu * gi * inv;
        if (blockIdx.x == 0) { g_AB[t] = sA[t]; g_AB[90 + t] = sB[t]; }
    }
    __syncthreads();
    if (t >= 270) return;
    int p = t / 30;
    double a1 = 0, a2 = 0;
    int b0 = blockIdx.x * 16;
    for (int bb = 0; bb < 16; bb++) {
        int b = b0 + bb;
        float cnt = g_hist[b];
        if (cnt == 0.f) continue;
        float m1 = g_hist[NB + b], m2 = g_hist[2 * NB + b];
        float dc = ((float)b + 0.5f) * (1.0f / (float)NB);
        float alpha = rb2[t], beta = 0.f;
#pragma unroll
        for (int u = 0; u < 10; u++) {
            float A = sA[p * 10 + u], Bv = sB[p * 10 + u];
            if (fmaf(A, dc, Bv) > 0.f) {
                float w = rW2[p * 300 + (t - p * 30) * 10 + u];
                alpha = fmaf(w, Bv, alpha);
                beta  = fmaf(w, A,  beta);
            }
        }
        double a = alpha, be = beta;
        a1 += a * (double)cnt + be * (double)m1;
        a2 += a * a * (double)cnt + 2.0 * a * be * (double)m1 + be * be * (double)m2;
    }
    atomicAdd(&g_stats[2 * t],     a1);
    atomicAdd(&g_stats[2 * t + 1], a2);
}

// ---- launch 2: BN2 fold (FLOAT math) + LUT rows ----------------------------
__global__ void k_lutbn2(const float* __restrict__ rg2, const float* __restrict__ rbb2,
                         const float* __restrict__ rW2, const float* __restrict__ rb2,
                         const float* __restrict__ rW3, const float* __restrict__ rb3,
                         int E) {
    __shared__ float sc[270], sh[270], h1[90], h2[272];
    int t = threadIdx.x;
    if (t < 270) {
        // float fold: g_stats magnitudes ~1e6 -> float conversion error ~6e-8
        // relative; FP64 divisions here were the wall-time regression.
        float invE = 1.0f / (float)E;
        float mean = (float)g_stats[2 * t] * invE;
        float var  = (float)g_stats[2 * t + 1] * invE - mean * mean;
        if (var < 0.f) var = 0.f;
        float s = rg2[t] * rsqrtf(var + EPSV);
        sc[t] = s;
        sh[t] = rbb2[t] - mean * s;
    }
    float d = (float)blockIdx.x * (1.0f / (float)NLUT);
    if (t < 90) h1[t] = fmaxf(0.f, fmaf(g_AB[t], d, g_AB[90 + t]));
    __syncthreads();
    if (t < 270) {
        int p = t / 30;
        float z = rb2[t];
#pragma unroll
        for (int u = 0; u < 10; u++)
            z = fmaf(rW2[p * 300 + (t - p * 30) * 10 + u], h1[p * 10 + u], z);
        h2[t] = fmaxf(0.f, fmaf(z, sc[t], sh[t]));
    }
    __syncthreads();
    if (t < 80) {
        float R = 0.f;
        if (t < 76) {
            int p = 0;
#pragma unroll
            for (int pp = 1; pp < 9; pp++) if (t >= c_Roff4[pp]) p = pp;
            int r = t - c_Roff4[p];
            R = rb3[p * 20 + r];
#pragma unroll
            for (int v = 0; v < 30; v++)
                R = fmaf(rW3[p * 600 + r * 30 + v], h2[p * 30 + v], R);
        }
        size_t b = blockIdx.x;
        g_lut2[(b * 80 + t) * 2] = R;
        if (b > 0) g_lut2[((b - 1) * 80 + t) * 2 + 1] = R;
    }
}

// ---- launch 3: main kernel (R7/R15 two-stage pipeline body, verbatim) ------
// per warp: 2 stages x 2 edges x 256 floats.
//   buf: R[0..76) | qi[76..94) | fi[94..112) | B2[112..250)
__global__ void __launch_bounds__(256, 2) k_main(
    const int* __restrict__ dst, const float* __restrict__ dist,
    const float* __restrict__ wa0, const float* __restrict__ wa1,
    const float* __restrict__ wa2, const float* __restrict__ wa3,
    const float* __restrict__ wa4, const float* __restrict__ wa5,
    const float* __restrict__ wa6, const float* __restrict__ wa7,
    const float* __restrict__ wa8,
    float* __restrict__ eout, int E) {
    __shared__ __align__(16) float S[8 * 1024];
    int lane = threadIdx.x & 31;
    float* base = S + ((threadIdx.x >> 5) << 10);

    const float* wb[9] = {wa0, wa1, wa2, wa3, wa4, wa5, wa6, wa7, wa8};

    int gw = (int)((blockIdx.x * blockDim.x + threadIdx.x) >> 5);
    int nw = (int)((gridDim.x * blockDim.x) >> 5);
    int nw2 = 2 * nw;

    const float* sp[9];
    int sstr[9], sb_[9], sq_[9];
#pragma unroll
    for (int it = 0; it < 9; it++) {
        uchar4 c = g_ct[it * 32 + lane];
        int sz   = c_SZ[c.x];
        sp[it]   = wb[c.x] + (int)c.y + 2 * gw * sz;
        sstr[it] = sz;
        sb_[it]  = (int)c.z * 2;
        sq_[it]  = (int)c.w * 2;
    }
    int bquad[3], bfp[3], bpr[3];
#pragma unroll
    for (int it = 0; it < 3; it++) {
        uchar4 c = g_bt[it * 32 + lane];
        bquad[it] = (int)c.x * 4;
        bfp[it]   = (int)c.y * 2;
        bpr[it]   = (int)c.z * 2;
    }

    int e = 2 * gw;
    if (e >= E) return;

    int   ndA0 = dst[e];
    float dA0  = dist[e];
    bool  vA   = (e + 1 < E);
    int   ndA1 = vA ? dst[e + 1] : ndA0;
    float dA1  = vA ? dist[e + 1] : dA0;
    int   ndB0 = 0, ndB1 = 0;
    float dB0 = 0.f, dB1 = 0.f;
    {
        int en = e + nw2;
        if (en < E) {
            ndB0 = dst[en];
            dB0  = dist[en];
            bool v = (en + 1 < E);
            ndB1 = v ? dst[en + 1] : ndB0;
            dB1  = v ? dist[en + 1] : dB0;
        }
    }

    // prologue: fill stage 0 with iter-0 node+LUT
    {
        float* s0 = base;
        float* s1 = base + 256;
        const float* np0 = g_node + (size_t)ndA0 * 36;
        const float* np1 = g_node + (size_t)ndA1 * 36;
        s0[76 + lane] = np0[lane];
        s1[76 + lane] = np1[lane];
        if (lane < 4) { s0[108 + lane] = np0[32 + lane]; s1[108 + lane] = np1[32 + lane]; }
        float td0 = dA0 * (float)NLUT;
        int i00 = max(0, min(NLUT - 1, (int)td0));
        float fr0 = td0 - (float)i00;
        float td1 = dA1 * (float)NLUT;
        int i01 = max(0, min(NLUT - 1, (int)td1));
        float fr1 = td1 - (float)i01;
        const float2* Lp0 = (const float2*)g_lut2 + (size_t)i00 * 80;
        const float2* Lp1 = (const float2*)g_lut2 + (size_t)i01 * 80;
#pragma unroll
        for (int it = 0; it < 3; it++) {
            int i = it * 32 + lane;
            if (it < 2 || lane < 12) {
                float2 ra = Lp0[i], rb = Lp1[i];
                s0[i] = fmaf(fr0, ra.y - ra.x, ra.x);
                s1[i] = fmaf(fr1, rb.y - rb.x, rb.x);
            }
        }
    }

    int p = 0;
    for (; e < E; e += nw2, p ^= 1) {
        float* s0 = base + (p << 9);
        float* s1 = s0 + 256;
        float* t0 = base + ((p ^ 1) << 9);
        float* t1 = t0 + 256;
        bool v1 = (e + 1 < E);

        // ---- 1. wj loads for THIS iteration
        float w0[9], w1[9];
#pragma unroll
        for (int it = 0; it < 9; it++) {
            w0[it] = __ldcs(sp[it]);
            w1[it] = v1 ? __ldcs(sp[it] + sstr[it]) : 0.f;
            sp[it] += sstr[it] * nw2;
        }

        // ---- 2. issue node+LUT loads for NEXT iteration
        const float* np0 = g_node + (size_t)ndB0 * 36;
        const float* np1 = g_node + (size_t)ndB1 * 36;
        float nq0 = np0[lane], nq1 = np1[lane];
        float nx0 = 0.f, nx1 = 0.f;
        if (lane < 4) { nx0 = np0[32 + lane]; nx1 = np1[32 + lane]; }
        float tdb0 = dB0 * (float)NLUT;
        int ib0 = max(0, min(NLUT - 1, (int)tdb0));
        float frb0 = tdb0 - (float)ib0;
        float tdb1 = dB1 * (float)NLUT;
        int ib1 = max(0, min(NLUT - 1, (int)tdb1));
        float frb1 = tdb1 - (float)ib1;
        const float2* LpB0 = (const float2*)g_lut2 + (size_t)ib0 * 80;
        const float2* LpB1 = (const float2*)g_lut2 + (size_t)ib1 * 80;
        float2 ra[3], rb[3];
#pragma unroll
        for (int it = 0; it < 3; it++) {
            int i = it * 32 + lane;
            if (it < 2 || lane < 12) { ra[it] = LpB0[i]; rb[it] = LpB1[i]; }
        }

        // ---- 3. prefetch dst/dist two iterations ahead
        int   ndC0 = 0, ndC1 = 0;
        float dC0 = 0.f, dC1 = 0.f;
        {
            int e2 = e + 2 * nw2;
            if (e2 < E) {
                ndC0 = dst[e2];
                dC0  = dist[e2];
                bool v = (e2 + 1 < E);
                ndC1 = v ? dst[e2 + 1] : ndC0;
                dC1  = v ? dist[e2 + 1] : dC0;
            }
        }

        // ---- 4. sync: stage-p buffers are ready
        __syncwarp();

        // ---- 5a. B build in stage p
#pragma unroll
        for (int it = 0; it < 3; it++) {
            if (it < 2 || lane < 5) {
                float4 Ra = *(const float4*)(s0 + bquad[it]);
                float2 fa = *(const float2*)(s0 + 94 + bfp[it]);
                *(float2*)(s0 + 112 + bpr[it]) =
                    make_float2(Ra.x * fa.x + Ra.y * fa.y, Ra.z * fa.x + Ra.w * fa.y);
                float4 Rb = *(const float4*)(s1 + bquad[it]);
                float2 fb = *(const float2*)(s1 + 94 + bfp[it]);
                *(float2*)(s1 + 112 + bpr[it]) =
                    make_float2(Rb.x * fb.x + Rb.y * fb.y, Rb.z * fb.x + Rb.w * fb.y);
            }
        }
        __syncwarp();

        // ---- 5b. contraction + reduce + output
        float acc0 = 0.f, acc1 = 0.f;
#pragma unroll
        for (int it = 0; it < 9; it++) {
            bool valid = (it < 8) || (lane < 3);   // 259 = 8*32+3
            float wv0 = valid ? w0[it] : 0.f;
            float wv1 = valid ? w1[it] : 0.f;
            float2 b0 = *(const float2*)(s0 + 112 + sb_[it]);
            float2 q0 = *(const float2*)(s0 + 76 + sq_[it]);
            acc0 = fmaf(wv0, fmaf(q0.x, b0.x, q0.y * b0.y), acc0);
            float2 b1 = *(const float2*)(s1 + 112 + sb_[it]);
            float2 q1 = *(const float2*)(s1 + 76 + sq_[it]);
            acc1 = fmaf(wv1, fmaf(q1.x, b1.x, q1.y * b1.y), acc1);
        }
#pragma unroll
        for (int o = 16; o > 0; o >>= 1) {
            acc0 += __shfl_xor_sync(0xFFFFFFFFu, acc0, o);
            acc1 += __shfl_xor_sync(0xFFFFFFFFu, acc1, o);
        }
        if (lane == 0) {
            float ev0 = expf(acc0);
            eout[e] = ev0;
            atomicAdd(&g_s[ndA0], ev0);
        }
        if (lane == 1 && v1) {
            float ev1 = expf(acc1);
            eout[e + 1] = ev1;
            atomicAdd(&g_s[ndA1], ev1);
        }

        // ---- 6. commit next iteration's node+LUT into stage p^1
        t0[76 + lane] = nq0;
        t1[76 + lane] = nq1;
        if (lane < 4) { t0[108 + lane] = nx0; t1[108 + lane] = nx1; }
#pragma unroll
        for (int it = 0; it < 3; it++) {
            int i = it * 32 + lane;
            if (it < 2 || lane < 12) {
                t0[i] = fmaf(frb0, ra[it].y - ra[it].x, ra[it].x);
                t1[i] = fmaf(frb1, rb[it].y - rb[it].x, rb[it].x);
            }
        }

        // ---- 7. rotate edge metadata
        ndA0 = ndB0; ndA1 = ndB1; dA0 = dB0; dA1 = dB1;
        ndB0 = ndC0; ndB1 = ndC1; dB0 = dC0; dB1 = dC1;
    }
}

// ---- launch 4: normalize ----------------------------------------------------
__global__ void k_div(const int* __restrict__ dst, float* __restrict__ out, int E) {
    int e = blockIdx.x * blockDim.x + threadIdx.x;
    if (e < E) out[e] = out[e] / g_s[dst[e]];
}

// ---------------------------------------------------------------------------
extern "C" void kernel_launch(void* const* d_in, const int* in_sizes, int n_in,
                              void* d_out, int out_size) {
    int b = (n_in == 26) ? 1 : 0;
    const int*   dst  = (const int*)d_in[b + 0];
    const float* dist = (const float*)d_in[b + 1];
    const float* f0   = (const float*)d_in[b + 2];
    const float* f1   = (const float*)d_in[b + 3];
    const float* f2   = (const float*)d_in[b + 4];
    const float* wq   = (const float*)d_in[b + 5];
    const float* wj[9];
    for (int i = 0; i < 9; i++) wj[i] = (const float*)d_in[b + 6 + i];  // a = k*3+l
    const float* rW1  = (const float*)d_in[b + 15];
    const float* rg1  = (const float*)d_in[b + 17];
    const float* rbb1 = (const float*)d_in[b + 18];
    const float* rW2  = (const float*)d_in[b + 19];
    const float* rb2  = (const float*)d_in[b + 20];
    const float* rg2  = (const float*)d_in[b + 21];
    const float* rbb2 = (const float*)d_in[b + 22];
    const float* rW3  = (const float*)d_in[b + 23];
    const float* rb3  = (const float*)d_in[b + 24];

    int E = in_sizes[b + 0];
    int N = in_sizes[b + 2] / 2;
    float* out = (float*)d_out;

    void *p_hist = nullptr, *p_s = nullptr, *p_stats = nullptr;
    cudaGetSymbolAddress(&p_hist, g_hist);
    cudaGetSymbolAddress(&p_s, g_s);
    cudaGetSymbolAddress(&p_stats, g_stats);
    cudaMemsetAsync(p_hist, 0, sizeof(float) * 3 * NB);
    cudaMemsetAsync(p_s, 0, sizeof(float) * NMAX);
    cudaMemsetAsync(p_stats, 0, sizeof(double) * 540);

    k_fused0<<<296, 256>>>(f0, f1, f2, wq, dist, N, E);            // launch 0
    k_statsAB<<<NB / 16, 288>>>(rW1, rg1, rbb1, rW2, rb2, E);      // launch 1
    k_lutbn2<<<NLUT + 1, 288>>>(rg2, rbb2, rW2, rb2, rW3, rb3, E); // launch 2
    k_main<<<296, 256>>>(dst, dist,                                 // launch 3 (profiled)
                         wj[0], wj[1], wj[2],
                         wj[3], wj[4], wj[5],
                         wj[6], wj[7], wj[8],
                         out, E);
    k_div<<<(E + 255) / 256, 256>>>(dst, out, E);                  // launch 4
}